// round 7
// baseline (speedup 1.0000x reference)
#include <cuda_runtime.h>
#include <math.h>

#define N_NODES 50000
#define N_EDGES 640000
#define F_IN 32
#define H 128
#define T_E 8
#define T_N 8
#define NLAYERS 12

// ---------------- static scratch (no allocations allowed) ----------------
__device__ __align__(16) float g_h   [(size_t)N_NODES * H];        // 25.6 MB
__device__ __align__(16) float g_h2  [(size_t)N_NODES * H];        // 25.6 MB
__device__ __align__(16) float g_agg8[(size_t)N_NODES * T_E * H];  // 204.8 MB
__device__ __align__(16) float g_msg [(size_t)N_NODES * H];        // 25.6 MB
__device__ __align__(16) float g_mid [(size_t)N_NODES * 2 * H];    // 51.2 MB

// node-type counting sort
__device__ int g_perm[N_NODES];
__device__ int g_cnt[T_N];
__device__ int g_off[T_N + 1];

// edge CSR by dst (deterministic aggregation)
__device__ int g_deg[N_NODES];
__device__ int g_row[N_NODES + 1];
__device__ int g_pos[N_NODES];
__device__ int g_eid [N_EDGES];
__device__ int g_esrc[N_EDGES];
__device__ int g_eet [N_EDGES];

// buffer selectors (avoid any host-side symbol lookups)
__device__ __forceinline__ const float* buf_c(int sel, const float* ext) {
    switch (sel) {
        case 0: return g_h;
        case 1: return g_h2;
        case 2: return g_agg8;
        case 3: return g_msg;
        case 4: return g_mid;
        default: return ext;
    }
}
__device__ __forceinline__ float* buf_m(int sel, float* ext) {
    switch (sel) {
        case 0: return g_h;
        case 1: return g_h2;
        case 3: return g_msg;
        case 4: return g_mid;
        default: return ext;
    }
}

// ---------------- counting sort of nodes by ntype ----------------
__global__ void sort_init() { if (threadIdx.x < T_N) g_cnt[threadIdx.x] = 0; }

__global__ void sort_hist(const int* __restrict__ nt) {
    int i = blockIdx.x * 256 + threadIdx.x;
    if (i < N_NODES) atomicAdd(&g_cnt[nt[i]], 1);
}

__global__ void sort_scan() {
    if (threadIdx.x == 0) {
        int s = 0;
        for (int t = 0; t < T_N; t++) { g_off[t] = s; s += g_cnt[t]; g_cnt[t] = g_off[t]; }
        g_off[T_N] = s;
    }
}

__global__ void sort_scatter(const int* __restrict__ nt) {
    int i = blockIdx.x * 256 + threadIdx.x;
    if (i < N_NODES) {
        int p = atomicAdd(&g_cnt[nt[i]], 1);
        g_perm[p] = i;   // order within a type is nondeterministic; results are
                         // permutation-invariant per node, so output bits are not.
    }
}

// ---------------- CSR build (per call; deterministic result) ----------------
__global__ void csr_zero() {
    int i = blockIdx.x * 256 + threadIdx.x;
    if (i < N_NODES) g_deg[i] = 0;
}

__global__ void csr_hist(const int* __restrict__ dst) {
    int e = blockIdx.x * 256 + threadIdx.x;
    if (e < N_EDGES) atomicAdd(&g_deg[dst[e]], 1);
}

// single-block exclusive scan over 50000 degrees
__global__ void __launch_bounds__(1024) csr_scan() {
    __shared__ int part[1024];
    const int CH = (N_NODES + 1023) / 1024;  // 49
    int t = threadIdx.x;
    int s = 0;
    for (int j = 0; j < CH; j++) {
        int i = t * CH + j;
        if (i < N_NODES) s += g_deg[i];
    }
    part[t] = s;
    __syncthreads();
    // Hillis-Steele inclusive scan
    for (int off = 1; off < 1024; off <<= 1) {
        int v = (t >= off) ? part[t - off] : 0;
        __syncthreads();
        part[t] += v;
        __syncthreads();
    }
    int base = (t == 0) ? 0 : part[t - 1];
    for (int j = 0; j < CH; j++) {
        int i = t * CH + j;
        if (i < N_NODES) { g_row[i] = base; g_pos[i] = base; base += g_deg[i]; }
    }
    if (t == 1023) g_row[N_NODES] = part[1023];
}

__global__ void csr_fill(const int* __restrict__ dst) {
    int e = blockIdx.x * 256 + threadIdx.x;
    if (e < N_EDGES) {
        int p = atomicAdd(&g_pos[dst[e]], 1);
        g_eid[p] = e;
    }
}

// stable order: insertion-sort each dst's edge list by edge id, then gather src/etype
__global__ void csr_sort(const int* __restrict__ src, const int* __restrict__ et) {
    int d = blockIdx.x * 128 + threadIdx.x;
    if (d >= N_NODES) return;
    int lo = g_row[d], hi = g_row[d + 1];
    for (int i = lo + 1; i < hi; i++) {
        int key = g_eid[i];
        int j = i - 1;
        while (j >= lo && g_eid[j] > key) { g_eid[j + 1] = g_eid[j]; j--; }
        g_eid[j + 1] = key;
    }
    for (int p = lo; p < hi; p++) {
        int e = g_eid[p];
        g_esrc[p] = src[e];
        g_eet[p]  = et[e];
    }
}

// ---------------- input projection: h = tanh(x @ W_in + b_in) ----------------
__global__ void __launch_bounds__(128) input_gemm(
    const float* __restrict__ x, const float* __restrict__ W,
    const float* __restrict__ b)
{
    __shared__ float xs[F_IN];
    int n = blockIdx.x;
    if (threadIdx.x < F_IN) xs[threadIdx.x] = x[n * F_IN + threadIdx.x];
    __syncthreads();
    int c = threadIdx.x;
    float s = b[c];
#pragma unroll
    for (int k = 0; k < F_IN; k++) s += xs[k] * W[k * H + c];
    g_h[(size_t)n * H + c] = tanhf(s);
}

// ---------------- deterministic aggregation ----------------
// agg8[d, t, c] = sum over edges (s->d, type t) of h[s, c], in stable CSR order.
// One block per dst, one thread per column; also zero-fills absent etypes.
__global__ void __launch_bounds__(128) aggregate(int hsel) {
    const float* __restrict__ h = (hsel == 0) ? g_h : g_h2;
    int d = blockIdx.x;
    int c = threadIdx.x;
    int lo = g_row[d], hi = g_row[d + 1];
    float acc[T_E];
#pragma unroll
    for (int t = 0; t < T_E; t++) acc[t] = 0.f;
    for (int p = lo; p < hi; p++) {
        int s = __ldg(&g_esrc[p]);
        int t = __ldg(&g_eet[p]);
        float v = h[(size_t)s * H + c];
#pragma unroll
        for (int u = 0; u < T_E; u++)
            if (u == t) acc[u] += v;
    }
    float* o = g_agg8 + (size_t)d * (T_E * H) + c;
#pragma unroll
    for (int t = 0; t < T_E; t++) o[(size_t)t * H] = acc[t];
}

// ---------------- tiled fp32 GEMM with tanh epilogue ----------------
// C[r,:] = tanh( [A0[r] | A1[r]] @ [B rows 0..K0 | B rows K0..K] + bias )
// TYPED: rows indirected via g_perm, row range per blockIdx.z from g_off,
//        B0 advanced by z*strideB (B1 = contiguous continuation of B0).
#define BM 128
#define BN 64
#define BK 16

template<bool TYPED>
__global__ void __launch_bounds__(256) gemm_tanh(
    int a0sel, int lda0,
    int a1sel, int lda1,
    int K0, int K,
    const float* __restrict__ B0,
    const float* __restrict__ B1,
    int Ncols,
    long long strideB,
    const float* __restrict__ bias,
    int csel, float* cext, int ldc,
    int M)
{
    __shared__ float As[BK][BM + 4];
    __shared__ float Bs[BK][BN];

    const float* __restrict__ A0 = buf_c(a0sel, nullptr);
    const float* __restrict__ A1 = buf_c(a1sel, nullptr);
    float* __restrict__ C = buf_m(csel, cext);

    int m_lo = 0, m_hi = M;
    const float* Bb0 = B0;
    const float* Bb1 = B1;
    if (TYPED) {
        int t = blockIdx.z;
        m_lo = g_off[t];
        m_hi = g_off[t + 1];
        Bb0 = B0 + (long long)t * strideB;
        Bb1 = Bb0 + (long long)K0 * Ncols;
    }
    int m0 = m_lo + blockIdx.x * BM;
    if (m0 >= m_hi) return;
    int n0 = blockIdx.y * BN;

    int tid = threadIdx.x;
    // A load: 128 rows x 16 k, 8 elems (2 float4) per thread
    int am  = tid & 127;
    int akq = tid >> 7;            // 0..1 -> k offsets akq*8 .. akq*8+7
    int arow = m0 + am;
    bool avalid = arow < m_hi;
    int ar = avalid ? (TYPED ? g_perm[arow] : arow) : 0;

    // B load: 16 k x 64 n, 1 float4 per thread
    int bn4 = (tid & 15) * 4;
    int bk  = tid >> 4;            // 0..15

    // compute mapping: 8 rows x 4 cols per thread
    int ty = tid >> 4;             // 0..15 -> rows ty*8 .. ty*8+7
    int tx = tid & 15;             // cols tx*4 .. tx*4+3

    float acc[8][4];
#pragma unroll
    for (int i = 0; i < 8; i++)
#pragma unroll
        for (int j = 0; j < 4; j++) acc[i][j] = 0.f;

    for (int kt = 0; kt < K; kt += BK) {
        // ---- load A tile ----
#pragma unroll
        for (int q = 0; q < 2; q++) {
            int kg = kt + akq * 8 + q * 4;
            float4 a;
            if (avalid) {
                const float* Ap; int kl;
                if (kg < K0) { Ap = A0 + (size_t)ar * lda0; kl = kg; }
                else         { Ap = A1 + (size_t)ar * lda1; kl = kg - K0; }
                a = *(const float4*)(Ap + kl);
            } else {
                a = make_float4(0.f, 0.f, 0.f, 0.f);
            }
            int kb = akq * 8 + q * 4;
            As[kb + 0][am] = a.x;
            As[kb + 1][am] = a.y;
            As[kb + 2][am] = a.z;
            As[kb + 3][am] = a.w;
        }
        // ---- load B tile ----
        {
            int kgb = kt + bk;
            const float* Bp = (kgb < K0) ? (Bb0 + (size_t)kgb * Ncols)
                                         : (Bb1 + (size_t)(kgb - K0) * Ncols);
            float4 b = *(const float4*)(Bp + n0 + bn4);
            *(float4*)&Bs[bk][bn4] = b;
        }
        __syncthreads();
        // ---- compute ----
#pragma unroll
        for (int k = 0; k < BK; k++) {
            float4 a0 = *(const float4*)&As[k][ty * 8];
            float4 a1 = *(const float4*)&As[k][ty * 8 + 4];
            float4 bv = *(const float4*)&Bs[k][tx * 4];
            float aa[8] = {a0.x, a0.y, a0.z, a0.w, a1.x, a1.y, a1.z, a1.w};
            float bb[4] = {bv.x, bv.y, bv.z, bv.w};
#pragma unroll
            for (int i = 0; i < 8; i++)
#pragma unroll
                for (int j = 0; j < 4; j++)
                    acc[i][j] += aa[i] * bb[j];
        }
        __syncthreads();
    }

    // ---- epilogue: bias + tanh, guarded rows ----
#pragma unroll
    for (int i = 0; i < 8; i++) {
        int r = m0 + ty * 8 + i;
        if (r < m_hi) {
            int rg = TYPED ? g_perm[r] : r;
#pragma unroll
            for (int j = 0; j < 4; j++) {
                int c = n0 + tx * 4 + j;
                float v = acc[i][j];
                if (bias) v += bias[c];
                C[(size_t)rg * ldc + c] = tanhf(v);
            }
        }
    }
}

// ---------------- launcher (kernel launches ONLY; no other CUDA APIs) ----------------
extern "C" void kernel_launch(void* const* d_in, const int* in_sizes, int n_in,
                              void* d_out, int out_size)
{
    const float* x      = (const float*)d_in[0];
    const int*   src    = (const int*)d_in[1];
    const int*   dst    = (const int*)d_in[2];
    const int*   et     = (const int*)d_in[3];
    const int*   nt     = (const int*)d_in[4];
    const float* W_in   = (const float*)d_in[5];
    const float* b_in   = (const float*)d_in[6];
    const float* W_rel  = (const float*)d_in[7];   // (12, 8, 128, 128)
    const float* W_loop = (const float*)d_in[8];   // (12, 128, 128)
    const float* b_rel  = (const float*)d_in[9];   // (12, 128)
    const float* W_up1  = (const float*)d_in[10];  // (12, 8, 256, 256)
    const float* W_up2  = (const float*)d_in[11];  // (12, 8, 384, 128)
    float* out = (float*)d_out;

    // node counting-sort by type
    sort_init<<<1, 32>>>();
    sort_hist<<<(N_NODES + 255) / 256, 256>>>(nt);
    sort_scan<<<1, 32>>>();
    sort_scatter<<<(N_NODES + 255) / 256, 256>>>(nt);

    // edge CSR by dst, stable within-dst order
    csr_zero<<<(N_NODES + 255) / 256, 256>>>();
    csr_hist<<<(N_EDGES + 255) / 256, 256>>>(dst);
    csr_scan<<<1, 1024>>>();
    csr_fill<<<(N_EDGES + 255) / 256, 256>>>(dst);
    csr_sort<<<(N_NODES + 127) / 128, 128>>>(src, et);

    // h = tanh(x @ W_in + b_in)
    input_gemm<<<N_NODES, 128>>>(x, W_in, b_in);

    int hsel = 0;                           // 0 -> g_h, 1 -> g_h2
    const int MT = (N_NODES + BM - 1) / BM; // 391

    for (int l = 0; l < NLAYERS; l++) {
        // agg8[d, t, :] = sum of h[src] over edges (src->d, type t)
        aggregate<<<N_NODES, 128>>>(hsel);

        // msg = tanh([agg8 | h] @ [W_rel_l ; W_loop_l] + b_rel_l)   (K = 1152)
        {
            dim3 g(MT, H / BN, 1);
            gemm_tanh<false><<<g, 256>>>(
                /*A0*/ 2, T_E * H, /*A1*/ hsel, H,
                T_E * H, T_E * H + H,
                W_rel  + (long long)l * T_E * H * H,
                W_loop + (long long)l * H * H,
                H, 0,
                b_rel + l * H,
                /*C*/ 3, nullptr, H, N_NODES);
        }
        // mid = tanh([h | msg] @ W_up1[l, ntype])   (K = 256, out 256, typed)
        {
            dim3 g(MT, (2 * H) / BN, T_N);
            gemm_tanh<true><<<g, 256>>>(
                /*A0*/ hsel, H, /*A1*/ 3, H,
                H, 2 * H,
                W_up1 + (long long)l * T_N * 2 * H * 2 * H, nullptr,
                2 * H, (long long)(2 * H) * (2 * H),
                nullptr,
                /*C*/ 4, nullptr, 2 * H, N_NODES);
        }
        // h_next = tanh([h | mid] @ W_up2[l, ntype])   (K = 384, out 128, typed)
        {
            dim3 g(MT, H / BN, T_N);
            int csel = (l == NLAYERS - 1) ? 5 : (1 - hsel);
            gemm_tanh<true><<<g, 256>>>(
                /*A0*/ hsel, H, /*A1*/ 4, 2 * H,
                H, 3 * H,
                W_up2 + (long long)l * T_N * 3 * H * H, nullptr,
                H, (long long)(3 * H) * H,
                nullptr,
                csel, out, H, N_NODES);
        }
        hsel = 1 - hsel;
    }
}